// round 9
// baseline (speedup 1.0000x reference)
#include <cuda_runtime.h>
#include <cuda_bf16.h>
#include <cstdint>

// Embedding gather: out[token, :] = table[ids[token], :]
// ids: [32*8192] int32, table: [256,256] f32, out: [32*8192, 256] f32.
//
// R9: counting-sort by vocab id (only 256 ids, each row reused ~1024x), then
// stream output grouped by id so each warp loads a table row into registers
// ONCE per run and issues stores only. This removes the gather-LDG half of
// the l1tex wavefront traffic, which profiling shows is the top unit (70-78%)
// in every prior variant. Stores stay lane-contiguous STG.128 streaming (.cs).
//
// K1: per-block smem histogram -> g_block_hist
// K2: per-id prefix over blocks + vocab exclusive scan (1 block)
// K3: scatter packed (token<<8 | id) into sorted order
// K4: warp processes 16 sorted entries; reload row regs only on id change;
//     2x STG.128 per token (512B lane-contiguous each).
// Output is deterministic: any permutation within an id bucket writes the
// same bytes.

static constexpr int TOKENS      = 32 * 8192;     // 262144
static constexpr int VOCAB       = 256;
static constexpr int EMBED       = 256;
static constexpr int VEC_PER_ROW = EMBED / 4;     // 64 float4 per row
static constexpr int HB          = 256;           // histogram/scatter blocks
static constexpr int TOK_PER_HB  = TOKENS / HB;   // 1024
static constexpr int K4_BLOCKS   = 2048;
static constexpr int ENT_PER_WARP= 16;            // sorted entries per warp

__device__ int g_block_hist[HB * VOCAB];      // per-block id counts
__device__ int g_block_part[HB * VOCAB];      // excl prefix over blocks per id
__device__ int g_vocab_base[VOCAB];           // excl prefix over ids
__device__ int g_sorted[TOKENS];              // (token << 8) | id

// ── K1: per-block histogram ────────────────────────────────────────────────
__global__ __launch_bounds__(256)
void k1_hist(const int* __restrict__ ids)
{
    __shared__ int h[VOCAB];
    h[threadIdx.x] = 0;
    __syncthreads();
    const int base = blockIdx.x * TOK_PER_HB;
    #pragma unroll
    for (int k = 0; k < TOK_PER_HB / 256; k++) {
        int id = __ldg(&ids[base + k * 256 + threadIdx.x]);
        atomicAdd(&h[id], 1);
    }
    __syncthreads();
    g_block_hist[blockIdx.x * VOCAB + threadIdx.x] = h[threadIdx.x];
}

// ── K2: prefix over blocks per id, then exclusive scan over ids ───────────
__global__ __launch_bounds__(256)
void k2_scan()
{
    const int v = threadIdx.x;
    int run = 0;
    #pragma unroll 4
    for (int b = 0; b < HB; b++) {
        int c = g_block_hist[b * VOCAB + v];
        g_block_part[b * VOCAB + v] = run;
        run += c;
    }
    // exclusive scan of per-id totals (Hillis-Steele inclusive, then shift)
    __shared__ int s[VOCAB];
    const int own = run;
    s[v] = run;
    __syncthreads();
    #pragma unroll
    for (int off = 1; off < VOCAB; off <<= 1) {
        int add = (v >= off) ? s[v - off] : 0;
        __syncthreads();
        s[v] += add;
        __syncthreads();
    }
    g_vocab_base[v] = s[v] - own;   // exclusive
}

// ── K3: scatter packed entries into sorted order ───────────────────────────
__global__ __launch_bounds__(256)
void k3_scatter(const int* __restrict__ ids)
{
    __shared__ int sc[VOCAB];
    sc[threadIdx.x] = 0;
    __syncthreads();
    const int base = blockIdx.x * TOK_PER_HB;
    #pragma unroll
    for (int k = 0; k < TOK_PER_HB / 256; k++) {
        int tok = base + k * 256 + threadIdx.x;
        int id  = __ldg(&ids[tok]);
        int r   = atomicAdd(&sc[id], 1);     // intra-block rank (any order ok)
        int pos = g_vocab_base[id] + g_block_part[blockIdx.x * VOCAB + id] + r;
        g_sorted[pos] = (tok << 8) | id;
    }
}

// ── K4: grouped output streamer ────────────────────────────────────────────
__global__ __launch_bounds__(256)
void k4_write(const float4* __restrict__ table4, float4* __restrict__ out4)
{
    const int lane  = threadIdx.x & 31;
    const int gwarp = blockIdx.x * (blockDim.x >> 5) + (threadIdx.x >> 5);
    const int base  = gwarp * ENT_PER_WARP;

    // lanes 0..15 hold the 16 entries; lane&15 keeps all lanes defined
    int packed = g_sorted[base + (lane & 15)];

    int    prev = -1;
    float4 v0, v1;
    #pragma unroll
    for (int k = 0; k < ENT_PER_WARP; k++) {
        int p   = __shfl_sync(0xffffffffu, packed, k);
        int id  = p & 0xFF;
        long long tok = (long long)(p >> 8);
        if (id != prev) {                        // warp-uniform branch
            const float4* row = &table4[id * VEC_PER_ROW];
            v0 = __ldg(&row[lane]);
            v1 = __ldg(&row[32 + lane]);
            prev = id;
        }
        float4* dst = &out4[tok * VEC_PER_ROW];
        __stcs(&dst[lane], v0);
        __stcs(&dst[32 + lane], v1);
    }
}

extern "C" void kernel_launch(void* const* d_in, const int* in_sizes, int n_in,
                              void* d_out, int out_size)
{
    const int*   ids   = (const int*)d_in[0];    // [32, 8192] int32
    const float* table = (const float*)d_in[1];  // [256, 256] f32
    float*       out   = (float*)d_out;          // [32, 8192, 256] f32

    k1_hist<<<HB, 256>>>(ids);
    k2_scan<<<1, 256>>>();
    k3_scatter<<<HB, 256>>>(ids);
    k4_write<<<K4_BLOCKS, 256>>>((const float4*)table, (float4*)out);
}

// round 10
// speedup vs baseline: 1.8943x; 1.8943x over previous
#include <cuda_runtime.h>
#include <cuda_bf16.h>

// Embedding gather: out[token, :] = table[ids[token], :]
// ids: [32*8192] int32, table: [256,256] f32, out: [32*8192, 256] f32.
//
// Final structure (R6): store-bandwidth-bound, 268 MB written. Each block
// owns one contiguous 16 KB output chunk; each thread runs 4 independent
// gather->store chains (k steps 4 KB) with lane-contiguous float4 accesses
// (512 B / 4 L1 lines per warp instruction — the proven-fast shape). The ids
// load is warp-uniform (one broadcast per warp per item); the 256 KB table
// stays L1/L2-resident. R10 single-variable change vs R6: default store
// policy instead of .cs evict-first, testing whether the L2->DRAM drain
// schedule (the binding resource per R2/R5/R6/R8/R9 convergence at
// 5.1-5.3 TB/s) prefers normal victim ordering.

static constexpr int       TOKENS       = 32 * 8192;          // 262144
static constexpr int       EMBED        = 256;
static constexpr int       VEC_PER_ROW  = EMBED / 4;          // 64 float4 per row
static constexpr long long TOTAL_VEC4   = (long long)TOKENS * VEC_PER_ROW; // 16,777,216
static constexpr int       ITEMS        = 4;                  // chains per thread
static constexpr int       THREADS      = 256;

__global__ __launch_bounds__(THREADS)
void embed_gather_kernel(const int* __restrict__ ids,
                         const float4* __restrict__ table4,
                         float4* __restrict__ out4)
{
    // Block b owns float4 range [b*1024, (b+1)*1024), k steps by 256 (4 KB).
    const long long base = (long long)blockIdx.x * (ITEMS * THREADS) + threadIdx.x;

    long long g[ITEMS];
    int       tok[ITEMS];
    float4    v[ITEMS];

    // Batched index loads (warp-uniform -> single broadcast L1 hit each).
    #pragma unroll
    for (int k = 0; k < ITEMS; k++) {
        g[k]   = base + k * THREADS;
        tok[k] = __ldg(&ids[g[k] >> 6]);
    }

    // Batched table loads (4 independent LDG.128; table resident in L1/L2).
    #pragma unroll
    for (int k = 0; k < ITEMS; k++) {
        v[k] = __ldg(&table4[(long long)tok[k] * VEC_PER_ROW + (g[k] & 63)]);
    }

    // Default-policy stores: contiguous 4 KB per block per k-step.
    #pragma unroll
    for (int k = 0; k < ITEMS; k++) {
        out4[g[k]] = v[k];
    }
}

extern "C" void kernel_launch(void* const* d_in, const int* in_sizes, int n_in,
                              void* d_out, int out_size)
{
    const int*   ids   = (const int*)d_in[0];    // [32, 8192] int32
    const float* table = (const float*)d_in[1];  // [256, 256] f32
    float*       out   = (float*)d_out;          // [32, 8192, 256] f32

    const int blocks = (int)(TOTAL_VEC4 / (ITEMS * THREADS));  // 16384

    embed_gather_kernel<<<blocks, THREADS>>>(
        ids, (const float4*)table, (float4*)out);
}